// round 1
// baseline (speedup 1.0000x reference)
#include <cuda_runtime.h>
#include <cuda_bf16.h>
#include <cstdint>

// ---------------- constants ----------------
#define HC 4
#define CDIM 256
#define KDIM 1024          // HC*C
#define MDIM 24            // HC*HC + 2*HC
#define TMAX_IT 20
#define RMS_EPS 1e-6f
#define SINK_EPS 1e-6f
#define POST_MULT 2.0f

#define MAX_TOKENS (8*4096)

// scratch (allocation-free: __device__ globals)
__device__ float g_xin [MAX_TOKENS * CDIM];   // 33.5 MB
__device__ float g_coef[MAX_TOKENS * 20];     // P[16] + h_post[4] per token

// ---------------- f32x2 helpers ----------------
__device__ __forceinline__ unsigned long long pk2(float lo, float hi) {
    unsigned long long r;
    asm("mov.b64 %0, {%1, %2};" : "=l"(r) : "f"(lo), "f"(hi));
    return r;
}
__device__ __forceinline__ void upk2(unsigned long long v, float& lo, float& hi) {
    asm("mov.b64 {%0, %1}, %2;" : "=f"(lo), "=f"(hi) : "l"(v));
}
__device__ __forceinline__ unsigned long long fma2(unsigned long long a,
                                                   unsigned long long b,
                                                   unsigned long long c) {
    unsigned long long d;
    asm("fma.rn.f32x2 %0, %1, %2, %3;" : "=l"(d) : "l"(a), "l"(b), "l"(c));
    return d;
}

__device__ __forceinline__ float sigmoidf_fast(float x) {
    return __fdividef(1.0f, 1.0f + __expf(-x));
}

// =====================================================================
// Kernel 1: per-token coefficients + x_in
//   64 tokens / CTA, 256 threads. Each warp: 8 tokens, 32 m-lanes.
// =====================================================================
#define KC1 32
#define XS_PAD 68   // 64 + 4: breaks same-token bank conflicts on transpose store

__global__ __launch_bounds__(256)
void k1_coeffs(const float* __restrict__ x,
               const float* __restrict__ phi,
               const float* __restrict__ bvec,
               const float* __restrict__ apre_p,
               const float* __restrict__ apost_p,
               const float* __restrict__ ares_p)
{
    __shared__ float xs[KC1][XS_PAD];    // transposed x chunk: xs[k][token]
    __shared__ float phis[KC1][32];      // phi chunk, m padded 24..31 with zeros

    const int tid  = threadIdx.x;
    const int lane = tid & 31;
    const int tg   = tid >> 5;           // warp id 0..7
    const int tok0 = blockIdx.x * 64;    // CTA token base
    const int t0   = tg * 8;             // warp's token offset in tile

    const float apre  = *apre_p;
    const float apost = *apost_p;
    const float ares  = *ares_p;

    // zero phi pad columns (m = 24..31) once
    for (int l = tid; l < KC1 * 8; l += 256)
        phis[l >> 3][24 + (l & 7)] = 0.0f;

    unsigned long long acc2[4];
    acc2[0] = acc2[1] = acc2[2] = acc2[3] = 0ull;

    for (int kc = 0; kc < KDIM; kc += KC1) {
        __syncthreads();
        // ---- load x chunk, transposed into xs[k][tok] ----
        #pragma unroll
        for (int r = 0; r < 2; r++) {
            int slot = r * 256 + tid;        // 0..511 : 64 tok x 8 kq
            int tok  = slot >> 3;
            int kq   = slot & 7;
            float4 v = *(const float4*)(x + (size_t)(tok0 + tok) * KDIM + kc + kq * 4);
            xs[kq*4+0][tok] = v.x;
            xs[kq*4+1][tok] = v.y;
            xs[kq*4+2][tok] = v.z;
            xs[kq*4+3][tok] = v.w;
        }
        // ---- load phi chunk (contiguous) ----
        #pragma unroll
        for (int l = tid; l < KC1 * MDIM; l += 256) {
            int k = l / MDIM;
            int m = l - k * MDIM;
            phis[k][m] = phi[kc * MDIM + l];
        }
        __syncthreads();
        // ---- inner: logits accumulate (f32x2 over token pairs) ----
        #pragma unroll 8
        for (int k = 0; k < KC1; k++) {
            float pm = phis[k][lane];
            unsigned long long pm2 = pk2(pm, pm);
            ulonglong2 xa = *(const ulonglong2*)(&xs[k][t0]);
            ulonglong2 xb = *(const ulonglong2*)(&xs[k][t0 + 4]);
            acc2[0] = fma2(xa.x, pm2, acc2[0]);
            acc2[1] = fma2(xa.y, pm2, acc2[1]);
            acc2[2] = fma2(xb.x, pm2, acc2[2]);
            acc2[3] = fma2(xb.y, pm2, acc2[3]);
        }
    }

    // unpack logits: l8[t] = logits[token t0+t][m=lane]
    float l8[8];
    #pragma unroll
    for (int j = 0; j < 4; j++) upk2(acc2[j], l8[2*j], l8[2*j+1]);

    const float bm = (lane < MDIM) ? bvec[lane] : 0.0f;

    // RMS norm per token
    float yv[8];
    #pragma unroll
    for (int t = 0; t < 8; t++) {
        float s = (lane < MDIM) ? l8[t] * l8[t] : 0.0f;
        s += __shfl_xor_sync(0xffffffffu, s, 16);
        s += __shfl_xor_sync(0xffffffffu, s, 8);
        s += __shfl_xor_sync(0xffffffffu, s, 4);
        s += __shfl_xor_sync(0xffffffffu, s, 2);
        s += __shfl_xor_sync(0xffffffffu, s, 1);
        float inv = rsqrtf(s * (1.0f / 24.0f) + RMS_EPS);
        yv[t] = l8[t] * inv + bm;
    }

    // ---- Sinkhorn: 2 tokens per warp-half, 4 pairs interleaved ----
    // lane layout per half: idx = lane&15, P[o][i] with i=idx&3, o=idx>>2
    float P[4];
    #pragma unroll
    for (int tp = 0; tp < 4; tp++) {
        int src = 8 + (lane & 15);
        float ra = __shfl_sync(0xffffffffu, yv[2*tp],     src);
        float rb = __shfl_sync(0xffffffffu, yv[2*tp + 1], src);
        float ysel = (lane < 16) ? ra : rb;
        P[tp] = __expf(ares * ysel);
    }
    #pragma unroll
    for (int it = 0; it < TMAX_IT; it++) {
        // row normalize (sum over i -> xor 1,2)
        #pragma unroll
        for (int tp = 0; tp < 4; tp++) {
            float s1 = P[tp] + __shfl_xor_sync(0xffffffffu, P[tp], 1);
            float s2 = s1    + __shfl_xor_sync(0xffffffffu, s1, 2);
            P[tp] = __fdividef(P[tp], s2 + SINK_EPS);
        }
        // col normalize (sum over o -> xor 4,8)
        #pragma unroll
        for (int tp = 0; tp < 4; tp++) {
            float s1 = P[tp] + __shfl_xor_sync(0xffffffffu, P[tp], 4);
            float s2 = s1    + __shfl_xor_sync(0xffffffffu, s1, 8);
            P[tp] = __fdividef(P[tp], s2 + SINK_EPS);
        }
    }

    // ---- store P ----
    #pragma unroll
    for (int tp = 0; tp < 4; tp++) {
        int tokA = tok0 + t0 + 2*tp;
        if (lane < 16) g_coef[(size_t)tokA * 20 + lane] = P[tp];
        else           g_coef[(size_t)(tokA + 1) * 20 + (lane - 16)] = P[tp];
    }

    // ---- h_post store + h_pre -> x_in ----
    #pragma unroll
    for (int t = 0; t < 8; t++) {
        int tok = tok0 + t0 + t;
        // h_post (lanes 0..3 write)
        float yp = __shfl_sync(0xffffffffu, yv[t], 4 + (lane & 3));
        if (lane < 4)
            g_coef[(size_t)tok * 20 + 16 + lane] = POST_MULT * sigmoidf_fast(apost * yp);

        // h_pre broadcast to all lanes
        float hp0 = sigmoidf_fast(apre * __shfl_sync(0xffffffffu, yv[t], 0));
        float hp1 = sigmoidf_fast(apre * __shfl_sync(0xffffffffu, yv[t], 1));
        float hp2 = sigmoidf_fast(apre * __shfl_sync(0xffffffffu, yv[t], 2));
        float hp3 = sigmoidf_fast(apre * __shfl_sync(0xffffffffu, yv[t], 3));

        const float4* xt = (const float4*)(x + (size_t)tok * KDIM);
        float4 sA = make_float4(0.f, 0.f, 0.f, 0.f);
        float4 sB = make_float4(0.f, 0.f, 0.f, 0.f);
        #pragma unroll
        for (int i = 0; i < HC; i++) {
            float hp = (i == 0) ? hp0 : (i == 1) ? hp1 : (i == 2) ? hp2 : hp3;
            float4 a = xt[i * 64 + lane];
            float4 b = xt[i * 64 + 32 + lane];
            sA.x = fmaf(hp, a.x, sA.x); sA.y = fmaf(hp, a.y, sA.y);
            sA.z = fmaf(hp, a.z, sA.z); sA.w = fmaf(hp, a.w, sA.w);
            sB.x = fmaf(hp, b.x, sB.x); sB.y = fmaf(hp, b.y, sB.y);
            sB.z = fmaf(hp, b.z, sB.z); sB.w = fmaf(hp, b.w, sB.w);
        }
        float4* xi = (float4*)(g_xin + (size_t)tok * CDIM);
        xi[lane]      = sA;
        xi[32 + lane] = sB;
    }
}

// =====================================================================
// Kernel 2: f_out = Xin @ W^T (f32x2 tiled GEMM) + fused epilogue
//   32 tokens / CTA, 256 threads, each thread: 4 tokens x 8 c
// =====================================================================
#define TT2 32
#define KC2 32

__global__ __launch_bounds__(256)
void k2_gemm_out(const float* __restrict__ x,
                 const float* __restrict__ W,
                 float* __restrict__ out)
{
    __shared__ float ws[KC2][CDIM];      // W chunk transposed: ws[k][c]
    __shared__ float xs[TT2][KC2];       // xin chunk
    __shared__ float cs[TT2][20];        // coeffs

    const int tid = threadIdx.x;
    const int cx  = tid & 31;            // c-lane
    const int tg  = tid >> 5;            // token group 0..7
    const int tb  = blockIdx.x * TT2;

    for (int l = tid; l < TT2 * 20; l += 256)
        cs[l / 20][l % 20] = g_coef[(size_t)tb * 20 + l];

    unsigned long long f2[4][4];         // [local token][c-pair jj]
    #pragma unroll
    for (int i = 0; i < 4; i++)
        #pragma unroll
        for (int j = 0; j < 4; j++) f2[i][j] = 0ull;

    for (int kc = 0; kc < CDIM; kc += KC2) {
        __syncthreads();
        // W chunk: thread tid owns row c=tid, transpose-store
        {
            const float4* wr = (const float4*)(W + (size_t)tid * CDIM + kc);
            #pragma unroll
            for (int kk = 0; kk < 8; kk++) {
                float4 w4 = wr[kk];
                ws[kk*4+0][tid] = w4.x;
                ws[kk*4+1][tid] = w4.y;
                ws[kk*4+2][tid] = w4.z;
                ws[kk*4+3][tid] = w4.w;
            }
        }
        // xin chunk
        {
            int tok = tid >> 3, kq = tid & 7;
            float4 v = *(const float4*)(g_xin + (size_t)(tb + tok) * CDIM + kc + kq * 4);
            *(float4*)&xs[tok][kq * 4] = v;
        }
        __syncthreads();
        #pragma unroll 8
        for (int k = 0; k < KC2; k++) {
            unsigned long long a2[4];
            #pragma unroll
            for (int i = 0; i < 4; i++) {
                float a = xs[tg * 4 + i][k];
                a2[i] = pk2(a, a);
            }
            ulonglong2 wA = *(const ulonglong2*)(&ws[k][cx * 4]);
            ulonglong2 wB = *(const ulonglong2*)(&ws[k][128 + cx * 4]);
            #pragma unroll
            for (int i = 0; i < 4; i++) {
                f2[i][0] = fma2(a2[i], wA.x, f2[i][0]);
                f2[i][1] = fma2(a2[i], wA.y, f2[i][1]);
                f2[i][2] = fma2(a2[i], wB.x, f2[i][2]);
                f2[i][3] = fma2(a2[i], wB.y, f2[i][3]);
            }
        }
    }

    // ---- epilogue: out[t][o][c] = sum_i P[o][i]*x[t][i][c] + hpost[o]*f[t][c]
    #pragma unroll
    for (int i = 0; i < 4; i++) {
        int tl  = tg * 4 + i;
        int tok = tb + tl;
        const float4* xt = (const float4*)(x + (size_t)tok * KDIM);
        float4 xa[HC], xb[HC];
        #pragma unroll
        for (int ii = 0; ii < HC; ii++) {
            xa[ii] = xt[ii * 64 + cx];
            xb[ii] = xt[ii * 64 + 32 + cx];
        }
        float4 fA, fB;
        upk2(f2[i][0], fA.x, fA.y);
        upk2(f2[i][1], fA.z, fA.w);
        upk2(f2[i][2], fB.x, fB.y);
        upk2(f2[i][3], fB.z, fB.w);

        float4* outp = (float4*)(out + (size_t)tok * (HC * CDIM));
        #pragma unroll
        for (int o = 0; o < HC; o++) {
            float hp = cs[tl][16 + o];
            float4 r0 = make_float4(hp*fA.x, hp*fA.y, hp*fA.z, hp*fA.w);
            float4 r1 = make_float4(hp*fB.x, hp*fB.y, hp*fB.z, hp*fB.w);
            #pragma unroll
            for (int ii = 0; ii < HC; ii++) {
                float p = cs[tl][o * 4 + ii];
                r0.x = fmaf(p, xa[ii].x, r0.x); r0.y = fmaf(p, xa[ii].y, r0.y);
                r0.z = fmaf(p, xa[ii].z, r0.z); r0.w = fmaf(p, xa[ii].w, r0.w);
                r1.x = fmaf(p, xb[ii].x, r1.x); r1.y = fmaf(p, xb[ii].y, r1.y);
                r1.z = fmaf(p, xb[ii].z, r1.z); r1.w = fmaf(p, xb[ii].w, r1.w);
            }
            outp[o * 64 + cx]      = r0;
            outp[o * 64 + 32 + cx] = r1;
        }
    }
}

// =====================================================================
extern "C" void kernel_launch(void* const* d_in, const int* in_sizes, int n_in,
                              void* d_out, int out_size)
{
    const float* x     = (const float*)d_in[0];
    const float* phi   = (const float*)d_in[1];
    const float* bvec  = (const float*)d_in[2];
    const float* apre  = (const float*)d_in[3];
    const float* apost = (const float*)d_in[4];
    const float* ares  = (const float*)d_in[5];
    const float* W     = (const float*)d_in[6];
    float* out = (float*)d_out;

    int tokens = in_sizes[0] / KDIM;

    k1_coeffs<<<tokens / 64, 256>>>(x, phi, bvec, apre, apost, ares);
    k2_gemm_out<<<tokens / TT2, 256>>>(x, W, out);
}

// round 3
// speedup vs baseline: 1.0433x; 1.0433x over previous
#include <cuda_runtime.h>
#include <cuda_bf16.h>
#include <cstdint>

// ---------------- constants ----------------
#define HC 4
#define CDIM 256
#define KDIM 1024          // HC*C
#define MDIM 24            // HC*HC + 2*HC
#define TMAX_IT 20
#define RMS_EPS 1e-6f
#define SINK_EPS 1e-6f
#define POST_MULT 2.0f

#define TOK_TILE 64

// dynamic smem layout (floats)
//  s_xin : [0,     16384)   : xin[64][256]                 (64 KB)
//  s_ws  : [16384, 24576)   : ws[32][256]  (GEMM W chunk)  (32 KB)
//    -- phase A aliases the ws region:
//  s_xs  : [16384, 16384+2176)  : xs[32][68]
//  s_phi : [18560, 18560+1024)  : phis[32][32]
//  s_cs  : [24576, 25856)   : cs[64][20]                   (5 KB)
#define SM_XIN   0
#define SM_WS    16384
#define SM_XS    16384
#define SM_PHI   (16384 + 2176)
#define SM_CS    24576
#define SMEM_FLOATS (24576 + 64*20)
#define SMEM_BYTES  (SMEM_FLOATS * 4)   // 103424

// ---------------- f32x2 helpers ----------------
typedef unsigned long long u64;

__device__ __forceinline__ u64 pk2(float lo, float hi) {
    u64 r; asm("mov.b64 %0, {%1, %2};" : "=l"(r) : "f"(lo), "f"(hi)); return r;
}
__device__ __forceinline__ void upk2(u64 v, float& lo, float& hi) {
    asm("mov.b64 {%0, %1}, %2;" : "=f"(lo), "=f"(hi) : "l"(v));
}
__device__ __forceinline__ u64 fma2(u64 a, u64 b, u64 c) {
    u64 d; asm("fma.rn.f32x2 %0, %1, %2, %3;" : "=l"(d) : "l"(a), "l"(b), "l"(c)); return d;
}
__device__ __forceinline__ u64 mul2(u64 a, u64 b) {
    u64 d; asm("mul.rn.f32x2 %0, %1, %2;" : "=l"(d) : "l"(a), "l"(b)); return d;
}
__device__ __forceinline__ float sigmoidf_fast(float x) {
    return __fdividef(1.0f, 1.0f + __expf(-x));
}

// =====================================================================
// Fused kernel: 64 tokens/CTA, 256 threads (8 warps, 8 tokens/warp)
// =====================================================================
__global__ __launch_bounds__(256, 2)
void mhc_fused(const float* __restrict__ x,
               const float* __restrict__ phi,
               const float* __restrict__ bvec,
               const float* __restrict__ apre_p,
               const float* __restrict__ apost_p,
               const float* __restrict__ ares_p,
               const float* __restrict__ W,
               float* __restrict__ out)
{
    extern __shared__ float smem[];
    float* s_xin = smem + SM_XIN;
    float* s_ws  = smem + SM_WS;
    float* s_xs  = smem + SM_XS;
    float* s_phi = smem + SM_PHI;
    float* s_cs  = smem + SM_CS;

    const int tid  = threadIdx.x;
    const int lane = tid & 31;
    const int tg   = tid >> 5;           // warp id 0..7
    const int tok0 = blockIdx.x * TOK_TILE;
    const int t0   = tg * 8;             // warp's token offset in tile

    const float apre  = *apre_p;
    const float apost = *apost_p;
    const float ares  = *ares_p;

    // ---------------- Phase A: logits GEMM (x . phi) ----------------
    // zero phi pad columns (m = 24..31) once
    for (int l = tid; l < 32 * 8; l += 256)
        s_phi[(l >> 3) * 32 + 24 + (l & 7)] = 0.0f;

    u64 acc2[4];
    acc2[0] = acc2[1] = acc2[2] = acc2[3] = 0ull;

    for (int kc = 0; kc < KDIM; kc += 32) {
        __syncthreads();
        // load x chunk, transposed into xs[k][tok]
        #pragma unroll
        for (int r = 0; r < 2; r++) {
            int slot = r * 256 + tid;        // 0..511 : 64 tok x 8 kq
            int tok  = slot >> 3;
            int kq   = slot & 7;
            float4 v = *(const float4*)(x + (size_t)(tok0 + tok) * KDIM + kc + kq * 4);
            s_xs[(kq*4+0)*68 + tok] = v.x;
            s_xs[(kq*4+1)*68 + tok] = v.y;
            s_xs[(kq*4+2)*68 + tok] = v.z;
            s_xs[(kq*4+3)*68 + tok] = v.w;
        }
        // load phi chunk (contiguous)
        #pragma unroll
        for (int l = tid; l < 32 * MDIM; l += 256) {
            int k = l / MDIM;
            int m = l - k * MDIM;
            s_phi[k * 32 + m] = phi[kc * MDIM + l];
        }
        __syncthreads();
        #pragma unroll 8
        for (int k = 0; k < 32; k++) {
            float pm = s_phi[k * 32 + lane];
            u64 pm2 = pk2(pm, pm);
            ulonglong2 xa = *(const ulonglong2*)(&s_xs[k * 68 + t0]);
            ulonglong2 xb = *(const ulonglong2*)(&s_xs[k * 68 + t0 + 4]);
            acc2[0] = fma2(xa.x, pm2, acc2[0]);
            acc2[1] = fma2(xa.y, pm2, acc2[1]);
            acc2[2] = fma2(xb.x, pm2, acc2[2]);
            acc2[3] = fma2(xb.y, pm2, acc2[3]);
        }
    }

    float l8[8];
    #pragma unroll
    for (int j = 0; j < 4; j++) upk2(acc2[j], l8[2*j], l8[2*j+1]);

    const float bm = (lane < MDIM) ? bvec[lane] : 0.0f;

    // RMS norm per token
    float yv[8];
    #pragma unroll
    for (int t = 0; t < 8; t++) {
        float s = (lane < MDIM) ? l8[t] * l8[t] : 0.0f;
        s += __shfl_xor_sync(0xffffffffu, s, 16);
        s += __shfl_xor_sync(0xffffffffu, s, 8);
        s += __shfl_xor_sync(0xffffffffu, s, 4);
        s += __shfl_xor_sync(0xffffffffu, s, 2);
        s += __shfl_xor_sync(0xffffffffu, s, 1);
        float inv = rsqrtf(s * (1.0f / 24.0f) + RMS_EPS);
        yv[t] = l8[t] * inv + bm;
    }

    // ---------------- Phase B: Sinkhorn (2 tokens per warp-half) ----------------
    float P[4];
    #pragma unroll
    for (int tp = 0; tp < 4; tp++) {
        int src = 8 + (lane & 15);
        float ra = __shfl_sync(0xffffffffu, yv[2*tp],     src);
        float rb = __shfl_sync(0xffffffffu, yv[2*tp + 1], src);
        float ysel = (lane < 16) ? ra : rb;
        P[tp] = __expf(ares * ysel);
    }
    #pragma unroll
    for (int it = 0; it < TMAX_IT; it++) {
        #pragma unroll
        for (int tp = 0; tp < 4; tp++) {
            float s1 = P[tp] + __shfl_xor_sync(0xffffffffu, P[tp], 1);
            float s2 = s1    + __shfl_xor_sync(0xffffffffu, s1, 2);
            P[tp] = __fdividef(P[tp], s2 + SINK_EPS);
        }
        #pragma unroll
        for (int tp = 0; tp < 4; tp++) {
            float s1 = P[tp] + __shfl_xor_sync(0xffffffffu, P[tp], 4);
            float s2 = s1    + __shfl_xor_sync(0xffffffffu, s1, 8);
            P[tp] = __fdividef(P[tp], s2 + SINK_EPS);
        }
    }

    // store P to cs
    #pragma unroll
    for (int tp = 0; tp < 4; tp++) {
        int tl = t0 + 2*tp;
        if (lane < 16) s_cs[tl * 20 + lane] = P[tp];
        else           s_cs[(tl + 1) * 20 + (lane - 16)] = P[tp];
    }

    // ---------------- Phase C: h_post + h_pre -> xin (smem) ----------------
    #pragma unroll
    for (int t = 0; t < 8; t++) {
        int tl  = t0 + t;
        int tok = tok0 + tl;
        float yp = __shfl_sync(0xffffffffu, yv[t], 4 + (lane & 3));
        if (lane < 4)
            s_cs[tl * 20 + 16 + lane] = POST_MULT * sigmoidf_fast(apost * yp);

        float hp0 = sigmoidf_fast(apre * __shfl_sync(0xffffffffu, yv[t], 0));
        float hp1 = sigmoidf_fast(apre * __shfl_sync(0xffffffffu, yv[t], 1));
        float hp2 = sigmoidf_fast(apre * __shfl_sync(0xffffffffu, yv[t], 2));
        float hp3 = sigmoidf_fast(apre * __shfl_sync(0xffffffffu, yv[t], 3));

        const float4* xt = (const float4*)(x + (size_t)tok * KDIM);
        float4 sA = make_float4(0.f, 0.f, 0.f, 0.f);
        float4 sB = make_float4(0.f, 0.f, 0.f, 0.f);
        #pragma unroll
        for (int i = 0; i < HC; i++) {
            float hp = (i == 0) ? hp0 : (i == 1) ? hp1 : (i == 2) ? hp2 : hp3;
            float4 a = xt[i * 64 + lane];
            float4 b = xt[i * 64 + 32 + lane];
            sA.x = fmaf(hp, a.x, sA.x); sA.y = fmaf(hp, a.y, sA.y);
            sA.z = fmaf(hp, a.z, sA.z); sA.w = fmaf(hp, a.w, sA.w);
            sB.x = fmaf(hp, b.x, sB.x); sB.y = fmaf(hp, b.y, sB.y);
            sB.z = fmaf(hp, b.z, sB.z); sB.w = fmaf(hp, b.w, sB.w);
        }
        float4* xi = (float4*)(s_xin + tl * CDIM);
        xi[lane]      = sA;
        xi[32 + lane] = sB;
    }

    // ---------------- Phase D: f = xin @ W^T (+ fused epilogue) ----------------
    // each warp: 8 tokens x 256 c; each lane: 8 tokens x 8 c (pairs)
    const int cx = lane;
    u64 f2[8][4];
    #pragma unroll
    for (int i = 0; i < 8; i++)
        #pragma unroll
        for (int j = 0; j < 4; j++) f2[i][j] = 0ull;

    for (int kc = 0; kc < CDIM; kc += 32) {
        __syncthreads();
        // W chunk: thread tid owns row c = tid, transpose-store into ws[k][c]
        {
            const float4* wr = (const float4*)(W + (size_t)tid * CDIM + kc);
            #pragma unroll
            for (int kk = 0; kk < 8; kk++) {
                float4 w4 = wr[kk];
                s_ws[(kk*4+0)*CDIM + tid] = w4.x;
                s_ws[(kk*4+1)*CDIM + tid] = w4.y;
                s_ws[(kk*4+2)*CDIM + tid] = w4.z;
                s_ws[(kk*4+3)*CDIM + tid] = w4.w;
            }
        }
        __syncthreads();
        #pragma unroll 4
        for (int k = 0; k < 32; k += 2) {
            float2 av[8];
            #pragma unroll
            for (int i = 0; i < 8; i++)
                av[i] = *(const float2*)(&s_xin[(t0 + i) * CDIM + kc + k]);
            ulonglong2 wA0 = *(const ulonglong2*)(&s_ws[k * CDIM + cx * 4]);
            ulonglong2 wB0 = *(const ulonglong2*)(&s_ws[k * CDIM + 128 + cx * 4]);
            ulonglong2 wA1 = *(const ulonglong2*)(&s_ws[(k+1) * CDIM + cx * 4]);
            ulonglong2 wB1 = *(const ulonglong2*)(&s_ws[(k+1) * CDIM + 128 + cx * 4]);
            #pragma unroll
            for (int i = 0; i < 8; i++) {
                u64 a0 = pk2(av[i].x, av[i].x);
                u64 a1 = pk2(av[i].y, av[i].y);
                f2[i][0] = fma2(a0, wA0.x, f2[i][0]);
                f2[i][1] = fma2(a0, wA0.y, f2[i][1]);
                f2[i][2] = fma2(a0, wB0.x, f2[i][2]);
                f2[i][3] = fma2(a0, wB0.y, f2[i][3]);
                f2[i][0] = fma2(a1, wA1.x, f2[i][0]);
                f2[i][1] = fma2(a1, wA1.y, f2[i][1]);
                f2[i][2] = fma2(a1, wB1.x, f2[i][2]);
                f2[i][3] = fma2(a1, wB1.y, f2[i][3]);
            }
        }
    }

    // epilogue: out[t][o][c] = sum_i P[o][i]*x[t][i][c] + hpost[o]*f[t][c]
    #pragma unroll
    for (int i = 0; i < 8; i++) {
        int tl  = t0 + i;
        int tok = tok0 + tl;
        const u64* xb = (const u64*)(x + (size_t)tok * KDIM);
        // x pairs: half A at c = 4cx..4cx+3, half B at 128+4cx..
        ulonglong2 xpA[HC], xpB[HC];
        #pragma unroll
        for (int ii = 0; ii < HC; ii++) {
            xpA[ii] = *(const ulonglong2*)(xb + ii * 128 + cx * 2);
            xpB[ii] = *(const ulonglong2*)(xb + ii * 128 + 64 + cx * 2);
        }
        u64* ob = (u64*)(out + (size_t)tok * KDIM);
        #pragma unroll
        for (int o = 0; o < HC; o++) {
            float hp = s_cs[tl * 20 + 16 + o];
            u64 hp2 = pk2(hp, hp);
            u64 r0 = mul2(hp2, f2[i][0]);
            u64 r1 = mul2(hp2, f2[i][1]);
            u64 r2 = mul2(hp2, f2[i][2]);
            u64 r3 = mul2(hp2, f2[i][3]);
            #pragma unroll
            for (int ii = 0; ii < HC; ii++) {
                float p = s_cs[tl * 20 + o * 4 + ii];
                u64 p2 = pk2(p, p);
                r0 = fma2(p2, xpA[ii].x, r0);
                r1 = fma2(p2, xpA[ii].y, r1);
                r2 = fma2(p2, xpB[ii].x, r2);
                r3 = fma2(p2, xpB[ii].y, r3);
            }
            *(ulonglong2*)(ob + o * 128 + cx * 2)      = make_ulonglong2(r0, r1);
            *(ulonglong2*)(ob + o * 128 + 64 + cx * 2) = make_ulonglong2(r2, r3);
        }
    }
}

// =====================================================================
extern "C" void kernel_launch(void* const* d_in, const int* in_sizes, int n_in,
                              void* d_out, int out_size)
{
    const float* x     = (const float*)d_in[0];
    const float* phi   = (const float*)d_in[1];
    const float* bvec  = (const float*)d_in[2];
    const float* apre  = (const float*)d_in[3];
    const float* apost = (const float*)d_in[4];
    const float* ares  = (const float*)d_in[5];
    const float* W     = (const float*)d_in[6];
    float* out = (float*)d_out;

    int tokens = in_sizes[0] / KDIM;

    static bool attr_set = false;
    if (!attr_set) {
        cudaFuncSetAttribute(mhc_fused,
                             cudaFuncAttributeMaxDynamicSharedMemorySize, SMEM_BYTES);
        attr_set = true;
    }
    mhc_fused<<<tokens / TOK_TILE, 256, SMEM_BYTES>>>(
        x, phi, bvec, apre, apost, ares, W, out);
}

// round 4
// speedup vs baseline: 1.0450x; 1.0016x over previous
#include <cuda_runtime.h>
#include <cuda_bf16.h>
#include <cstdint>

// ---------------- constants ----------------
#define HC 4
#define CDIM 256
#define KDIM 1024          // HC*C
#define MDIM 24            // HC*HC + 2*HC
#define TMAX_IT 20
#define RMS_EPS 1e-6f
#define SINK_EPS 1e-6f
#define POST_MULT 2.0f

#define TOK_TILE 64

// dynamic smem layout (floats)
//  s_xin : [0,     16384)   : xin[64][256]                 (64 KB)
//  s_ws  : [16384, 24576)   : ws[32][256]  (GEMM W chunk)  (32 KB)
//    -- phase A aliases the ws region:
//  s_xs  : [16384, 16384+2176)  : xs[32][68]
//  s_phi : [18560, 18560+1024)  : phis[32][32]
//  s_cs  : [24576, 25856)   : cs[64][20]                   (5 KB)
#define SM_XIN   0
#define SM_WS    16384
#define SM_XS    16384
#define SM_PHI   (16384 + 2176)
#define SM_CS    24576
#define SMEM_FLOATS (24576 + 64*20)
#define SMEM_BYTES  (SMEM_FLOATS * 4)   // 103424

// ---------------- f32x2 helpers ----------------
typedef unsigned long long u64;

__device__ __forceinline__ u64 pk2(float lo, float hi) {
    u64 r; asm("mov.b64 %0, {%1, %2};" : "=l"(r) : "f"(lo), "f"(hi)); return r;
}
__device__ __forceinline__ void upk2(u64 v, float& lo, float& hi) {
    asm("mov.b64 {%0, %1}, %2;" : "=f"(lo), "=f"(hi) : "l"(v));
}
__device__ __forceinline__ u64 fma2(u64 a, u64 b, u64 c) {
    u64 d; asm("fma.rn.f32x2 %0, %1, %2, %3;" : "=l"(d) : "l"(a), "l"(b), "l"(c)); return d;
}
__device__ __forceinline__ u64 mul2(u64 a, u64 b) {
    u64 d; asm("mul.rn.f32x2 %0, %1, %2;" : "=l"(d) : "l"(a), "l"(b)); return d;
}
__device__ __forceinline__ float sigmoidf_fast(float x) {
    return __fdividef(1.0f, 1.0f + __expf(-x));
}

// =====================================================================
// Fused kernel: 64 tokens/CTA, 256 threads (8 warps, 8 tokens/warp)
// =====================================================================
__global__ __launch_bounds__(256, 2)
void mhc_fused(const float* __restrict__ x,
               const float* __restrict__ phi,
               const float* __restrict__ bvec,
               const float* __restrict__ apre_p,
               const float* __restrict__ apost_p,
               const float* __restrict__ ares_p,
               const float* __restrict__ W,
               float* __restrict__ out)
{
    extern __shared__ float smem[];
    float* s_xin = smem + SM_XIN;
    float* s_ws  = smem + SM_WS;
    float* s_xs  = smem + SM_XS;
    float* s_phi = smem + SM_PHI;
    float* s_cs  = smem + SM_CS;

    const int tid  = threadIdx.x;
    const int lane = tid & 31;
    const int tg   = tid >> 5;           // warp id 0..7
    const int tok0 = blockIdx.x * TOK_TILE;
    const int t0   = tg * 8;             // warp's token offset in tile

    const float apre  = *apre_p;
    const float apost = *apost_p;
    const float ares  = *ares_p;

    // ---------------- Phase A: logits GEMM (x . phi) ----------------
    // zero phi pad columns (m = 24..31) once
    for (int l = tid; l < 32 * 8; l += 256)
        s_phi[(l >> 3) * 32 + 24 + (l & 7)] = 0.0f;

    u64 acc2[4];
    acc2[0] = acc2[1] = acc2[2] = acc2[3] = 0ull;

    for (int kc = 0; kc < KDIM; kc += 32) {
        __syncthreads();
        // load x chunk, transposed into xs[k][tok]
        #pragma unroll
        for (int r = 0; r < 2; r++) {
            int slot = r * 256 + tid;        // 0..511 : 64 tok x 8 kq
            int tok  = slot >> 3;
            int kq   = slot & 7;
            float4 v = *(const float4*)(x + (size_t)(tok0 + tok) * KDIM + kc + kq * 4);
            s_xs[(kq*4+0)*68 + tok] = v.x;
            s_xs[(kq*4+1)*68 + tok] = v.y;
            s_xs[(kq*4+2)*68 + tok] = v.z;
            s_xs[(kq*4+3)*68 + tok] = v.w;
        }
        // load phi chunk (contiguous)
        #pragma unroll
        for (int l = tid; l < 32 * MDIM; l += 256) {
            int k = l / MDIM;
            int m = l - k * MDIM;
            s_phi[k * 32 + m] = phi[kc * MDIM + l];
        }
        __syncthreads();
        #pragma unroll 8
        for (int k = 0; k < 32; k++) {
            float pm = s_phi[k * 32 + lane];
            u64 pm2 = pk2(pm, pm);
            ulonglong2 xa = *(const ulonglong2*)(&s_xs[k * 68 + t0]);
            ulonglong2 xb = *(const ulonglong2*)(&s_xs[k * 68 + t0 + 4]);
            acc2[0] = fma2(xa.x, pm2, acc2[0]);
            acc2[1] = fma2(xa.y, pm2, acc2[1]);
            acc2[2] = fma2(xb.x, pm2, acc2[2]);
            acc2[3] = fma2(xb.y, pm2, acc2[3]);
        }
    }

    float l8[8];
    #pragma unroll
    for (int j = 0; j < 4; j++) upk2(acc2[j], l8[2*j], l8[2*j+1]);

    const float bm = (lane < MDIM) ? bvec[lane] : 0.0f;

    // RMS norm per token
    float yv[8];
    #pragma unroll
    for (int t = 0; t < 8; t++) {
        float s = (lane < MDIM) ? l8[t] * l8[t] : 0.0f;
        s += __shfl_xor_sync(0xffffffffu, s, 16);
        s += __shfl_xor_sync(0xffffffffu, s, 8);
        s += __shfl_xor_sync(0xffffffffu, s, 4);
        s += __shfl_xor_sync(0xffffffffu, s, 2);
        s += __shfl_xor_sync(0xffffffffu, s, 1);
        float inv = rsqrtf(s * (1.0f / 24.0f) + RMS_EPS);
        yv[t] = l8[t] * inv + bm;
    }

    // ---------------- Phase B: Sinkhorn (2 tokens per warp-half) ----------------
    float P[4];
    #pragma unroll
    for (int tp = 0; tp < 4; tp++) {
        int src = 8 + (lane & 15);
        float ra = __shfl_sync(0xffffffffu, yv[2*tp],     src);
        float rb = __shfl_sync(0xffffffffu, yv[2*tp + 1], src);
        float ysel = (lane < 16) ? ra : rb;
        P[tp] = __expf(ares * ysel);
    }
    #pragma unroll
    for (int it = 0; it < TMAX_IT; it++) {
        #pragma unroll
        for (int tp = 0; tp < 4; tp++) {
            float s1 = P[tp] + __shfl_xor_sync(0xffffffffu, P[tp], 1);
            float s2 = s1    + __shfl_xor_sync(0xffffffffu, s1, 2);
            P[tp] = __fdividef(P[tp], s2 + SINK_EPS);
        }
        #pragma unroll
        for (int tp = 0; tp < 4; tp++) {
            float s1 = P[tp] + __shfl_xor_sync(0xffffffffu, P[tp], 4);
            float s2 = s1    + __shfl_xor_sync(0xffffffffu, s1, 8);
            P[tp] = __fdividef(P[tp], s2 + SINK_EPS);
        }
    }

    // store P to cs
    #pragma unroll
    for (int tp = 0; tp < 4; tp++) {
        int tl = t0 + 2*tp;
        if (lane < 16) s_cs[tl * 20 + lane] = P[tp];
        else           s_cs[(tl + 1) * 20 + (lane - 16)] = P[tp];
    }

    // ---------------- Phase C: h_post + h_pre -> xin (smem) ----------------
    #pragma unroll
    for (int t = 0; t < 8; t++) {
        int tl  = t0 + t;
        int tok = tok0 + tl;
        float yp = __shfl_sync(0xffffffffu, yv[t], 4 + (lane & 3));
        if (lane < 4)
            s_cs[tl * 20 + 16 + lane] = POST_MULT * sigmoidf_fast(apost * yp);

        float hp0 = sigmoidf_fast(apre * __shfl_sync(0xffffffffu, yv[t], 0));
        float hp1 = sigmoidf_fast(apre * __shfl_sync(0xffffffffu, yv[t], 1));
        float hp2 = sigmoidf_fast(apre * __shfl_sync(0xffffffffu, yv[t], 2));
        float hp3 = sigmoidf_fast(apre * __shfl_sync(0xffffffffu, yv[t], 3));

        const float4* xt = (const float4*)(x + (size_t)tok * KDIM);
        float4 sA = make_float4(0.f, 0.f, 0.f, 0.f);
        float4 sB = make_float4(0.f, 0.f, 0.f, 0.f);
        #pragma unroll
        for (int i = 0; i < HC; i++) {
            float hp = (i == 0) ? hp0 : (i == 1) ? hp1 : (i == 2) ? hp2 : hp3;
            float4 a = xt[i * 64 + lane];
            float4 b = xt[i * 64 + 32 + lane];
            sA.x = fmaf(hp, a.x, sA.x); sA.y = fmaf(hp, a.y, sA.y);
            sA.z = fmaf(hp, a.z, sA.z); sA.w = fmaf(hp, a.w, sA.w);
            sB.x = fmaf(hp, b.x, sB.x); sB.y = fmaf(hp, b.y, sB.y);
            sB.z = fmaf(hp, b.z, sB.z); sB.w = fmaf(hp, b.w, sB.w);
        }
        float4* xi = (float4*)(s_xin + tl * CDIM);
        xi[lane]      = sA;
        xi[32 + lane] = sB;
    }

    // ---------------- Phase D: f = xin @ W^T (+ fused epilogue) ----------------
    // each warp: 8 tokens x 256 c; each lane: 8 tokens x 8 c (pairs)
    const int cx = lane;
    u64 f2[8][4];
    #pragma unroll
    for (int i = 0; i < 8; i++)
        #pragma unroll
        for (int j = 0; j < 4; j++) f2[i][j] = 0ull;

    for (int kc = 0; kc < CDIM; kc += 32) {
        __syncthreads();
        // W chunk: thread tid owns row c = tid, transpose-store into ws[k][c]
        {
            const float4* wr = (const float4*)(W + (size_t)tid * CDIM + kc);
            #pragma unroll
            for (int kk = 0; kk < 8; kk++) {
                float4 w4 = wr[kk];
                s_ws[(kk*4+0)*CDIM + tid] = w4.x;
                s_ws[(kk*4+1)*CDIM + tid] = w4.y;
                s_ws[(kk*4+2)*CDIM + tid] = w4.z;
                s_ws[(kk*4+3)*CDIM + tid] = w4.w;
            }
        }
        __syncthreads();
        #pragma unroll 4
        for (int k = 0; k < 32; k += 2) {
            float2 av[8];
            #pragma unroll
            for (int i = 0; i < 8; i++)
                av[i] = *(const float2*)(&s_xin[(t0 + i) * CDIM + kc + k]);
            ulonglong2 wA0 = *(const ulonglong2*)(&s_ws[k * CDIM + cx * 4]);
            ulonglong2 wB0 = *(const ulonglong2*)(&s_ws[k * CDIM + 128 + cx * 4]);
            ulonglong2 wA1 = *(const ulonglong2*)(&s_ws[(k+1) * CDIM + cx * 4]);
            ulonglong2 wB1 = *(const ulonglong2*)(&s_ws[(k+1) * CDIM + 128 + cx * 4]);
            #pragma unroll
            for (int i = 0; i < 8; i++) {
                u64 a0 = pk2(av[i].x, av[i].x);
                u64 a1 = pk2(av[i].y, av[i].y);
                f2[i][0] = fma2(a0, wA0.x, f2[i][0]);
                f2[i][1] = fma2(a0, wA0.y, f2[i][1]);
                f2[i][2] = fma2(a0, wB0.x, f2[i][2]);
                f2[i][3] = fma2(a0, wB0.y, f2[i][3]);
                f2[i][0] = fma2(a1, wA1.x, f2[i][0]);
                f2[i][1] = fma2(a1, wA1.y, f2[i][1]);
                f2[i][2] = fma2(a1, wB1.x, f2[i][2]);
                f2[i][3] = fma2(a1, wB1.y, f2[i][3]);
            }
        }
    }

    // epilogue: out[t][o][c] = sum_i P[o][i]*x[t][i][c] + hpost[o]*f[t][c]
    #pragma unroll
    for (int i = 0; i < 8; i++) {
        int tl  = t0 + i;
        int tok = tok0 + tl;
        const u64* xb = (const u64*)(x + (size_t)tok * KDIM);
        // x pairs: half A at c = 4cx..4cx+3, half B at 128+4cx..
        ulonglong2 xpA[HC], xpB[HC];
        #pragma unroll
        for (int ii = 0; ii < HC; ii++) {
            xpA[ii] = *(const ulonglong2*)(xb + ii * 128 + cx * 2);
            xpB[ii] = *(const ulonglong2*)(xb + ii * 128 + 64 + cx * 2);
        }
        u64* ob = (u64*)(out + (size_t)tok * KDIM);
        #pragma unroll
        for (int o = 0; o < HC; o++) {
            float hp = s_cs[tl * 20 + 16 + o];
            u64 hp2 = pk2(hp, hp);
            u64 r0 = mul2(hp2, f2[i][0]);
            u64 r1 = mul2(hp2, f2[i][1]);
            u64 r2 = mul2(hp2, f2[i][2]);
            u64 r3 = mul2(hp2, f2[i][3]);
            #pragma unroll
            for (int ii = 0; ii < HC; ii++) {
                float p = s_cs[tl * 20 + o * 4 + ii];
                u64 p2 = pk2(p, p);
                r0 = fma2(p2, xpA[ii].x, r0);
                r1 = fma2(p2, xpA[ii].y, r1);
                r2 = fma2(p2, xpB[ii].x, r2);
                r3 = fma2(p2, xpB[ii].y, r3);
            }
            *(ulonglong2*)(ob + o * 128 + cx * 2)      = make_ulonglong2(r0, r1);
            *(ulonglong2*)(ob + o * 128 + 64 + cx * 2) = make_ulonglong2(r2, r3);
        }
    }
}

// =====================================================================
extern "C" void kernel_launch(void* const* d_in, const int* in_sizes, int n_in,
                              void* d_out, int out_size)
{
    const float* x     = (const float*)d_in[0];
    const float* phi   = (const float*)d_in[1];
    const float* bvec  = (const float*)d_in[2];
    const float* apre  = (const float*)d_in[3];
    const float* apost = (const float*)d_in[4];
    const float* ares  = (const float*)d_in[5];
    const float* W     = (const float*)d_in[6];
    float* out = (float*)d_out;

    int tokens = in_sizes[0] / KDIM;

    static bool attr_set = false;
    if (!attr_set) {
        cudaFuncSetAttribute(mhc_fused,
                             cudaFuncAttributeMaxDynamicSharedMemorySize, SMEM_BYTES);
        attr_set = true;
    }
    mhc_fused<<<tokens / TOK_TILE, 256, SMEM_BYTES>>>(
        x, phi, bvec, apre, apost, ares, W, out);
}

// round 6
// speedup vs baseline: 1.2523x; 1.1983x over previous
#include <cuda_runtime.h>
#include <cuda_bf16.h>
#include <cstdint>

#define HC 4
#define CDIM 256
#define KDIM 1024
#define MDIM 24
#define TMAX_IT 20
#define RMS_EPS 1e-6f
#define SINK_EPS 1e-6f
#define POST_MULT 2.0f
#define TOK 128
#define THREADS 512

// ---- smem byte offsets ----
#define OFF_CS 256                     // 128 tok x 20 floats
#define OFF_AH 16384                   // A hi bf16 [128 rows x 264 bf16] = 67584
#define OFF_AL 83968                   // A lo
#define OFF_B  151552                  // B chunk hi(32KB)+lo(32KB); phase-A bufs alias
#define OFF_D  16384                   // f fp32 [128][264] = 135168 (aliases A, ends at OFF_B)
#define D_STR  264
#define A_STR  528                     // bytes per A row (264 bf16)
#define XSB(b)  (OFF_B + (b)*21504)    // xs[32][132] floats
#define PHIB(b) (OFF_B + (b)*21504 + 16896)
#define SMEM_TOTAL 217088

typedef unsigned long long u64;

// W pre-packed, B-fragment-major: [kchunk 0..3][hi(32KB)|lo(32KB)]
// within a 32KB half: [ks 0..3][ns 0..31][lane 0..31][b0,b1 (8B)]
__device__ __align__(16) char g_wpk[4 * 65536];

// ---- helpers ----
__device__ __forceinline__ u64 pk2(float lo, float hi) {
    u64 r; asm("mov.b64 %0, {%1, %2};" : "=l"(r) : "f"(lo), "f"(hi)); return r;
}
__device__ __forceinline__ void upk2(u64 v, float& lo, float& hi) {
    asm("mov.b64 {%0, %1}, %2;" : "=f"(lo), "=f"(hi) : "l"(v));
}
__device__ __forceinline__ u64 fma2(u64 a, u64 b, u64 c) {
    u64 d; asm("fma.rn.f32x2 %0, %1, %2, %3;" : "=l"(d) : "l"(a), "l"(b), "l"(c)); return d;
}
__device__ __forceinline__ float sigmoidf_fast(float v) {
    return __fdividef(1.0f, 1.0f + __expf(-v));
}
__device__ __forceinline__ void split4(float4 v, uint2& h, uint2& l) {
    __nv_bfloat16 ax = __float2bfloat16(v.x), ay = __float2bfloat16(v.y),
                  az = __float2bfloat16(v.z), aw = __float2bfloat16(v.w);
    __nv_bfloat16 bx = __float2bfloat16(v.x - __bfloat162float(ax)),
                  by = __float2bfloat16(v.y - __bfloat162float(ay)),
                  bz = __float2bfloat16(v.z - __bfloat162float(az)),
                  bw = __float2bfloat16(v.w - __bfloat162float(aw));
    h.x = ((uint32_t)__bfloat16_as_ushort(ay) << 16) | __bfloat16_as_ushort(ax);
    h.y = ((uint32_t)__bfloat16_as_ushort(aw) << 16) | __bfloat16_as_ushort(az);
    l.x = ((uint32_t)__bfloat16_as_ushort(by) << 16) | __bfloat16_as_ushort(bx);
    l.y = ((uint32_t)__bfloat16_as_ushort(bw) << 16) | __bfloat16_as_ushort(bz);
}
__device__ __forceinline__ void mma_bf16(float4& d, uint4 a, uint2 b) {
    asm volatile("mma.sync.aligned.m16n8k16.row.col.f32.bf16.bf16.f32 "
        "{%0,%1,%2,%3}, {%4,%5,%6,%7}, {%8,%9}, {%0,%1,%2,%3};"
        : "+f"(d.x), "+f"(d.y), "+f"(d.z), "+f"(d.w)
        : "r"(a.x), "r"(a.y), "r"(a.z), "r"(a.w), "r"(b.x), "r"(b.y));
}

// =====================================================================
// W pack: fragment-major hi/lo bf16 (one-time, 65536 threads)
__global__ void w_pack(const float* __restrict__ W) {
    int i = blockIdx.x * 256 + threadIdx.x;
    int n = i >> 8, k = i & 255;
    float v = W[n * 256 + k];
    __nv_bfloat16 h = __float2bfloat16(v);
    __nv_bfloat16 l = __float2bfloat16(v - __bfloat162float(h));
    int kc = k >> 6, ks = (k & 63) >> 4, k_in = k & 15, ns = n >> 3;
    int lane = ((n & 7) << 2) | ((k_in >> 1) & 3);
    int off = (((ks * 32 + ns) * 32 + lane) << 3) + ((k_in >> 3) << 2) + ((k_in & 1) << 1);
    *(__nv_bfloat16*)(g_wpk + kc * 65536 + off)         = h;
    *(__nv_bfloat16*)(g_wpk + kc * 65536 + 32768 + off) = l;
}

// =====================================================================
__global__ __launch_bounds__(THREADS, 1)
void mhc_mma(const float* __restrict__ x, const float* __restrict__ phi,
             const float* __restrict__ bvec, const float* __restrict__ apre_p,
             const float* __restrict__ apost_p, const float* __restrict__ ares_p,
             float* __restrict__ out)
{
    extern __shared__ char smem[];
    float* s_cs = (float*)(smem + OFF_CS);
    const int tid = threadIdx.x, lane = tid & 31, wid = tid >> 5;
    const int tok0 = blockIdx.x * TOK;
    const int t0 = wid * 8;

    const float apre = *apre_p, apost = *apost_p, ares = *ares_p;

    // zero phi pads (m 24..31) in both buffers
    for (int l = tid; l < 512; l += THREADS) {
        int b = l >> 8, ll = l & 255;
        ((float*)(smem + PHIB(b)))[(ll >> 3) * 32 + 24 + (ll & 7)] = 0.0f;
    }

    // ---------- Phase A: logits = x . phi (double-buffered, 32-k chunks) ----------
    u64 acc2[4] = {0ull, 0ull, 0ull, 0ull};
    {
        for (int r = 0; r < 2; r++) {
            int slot = r * THREADS + tid, tk = slot >> 3, kq = slot & 7;
            float4 v = *(const float4*)(x + (size_t)(tok0 + tk) * KDIM + kq * 4);
            float* xs = (float*)(smem + XSB(0));
            xs[(kq*4+0)*132 + tk] = v.x; xs[(kq*4+1)*132 + tk] = v.y;
            xs[(kq*4+2)*132 + tk] = v.z; xs[(kq*4+3)*132 + tk] = v.w;
        }
        for (int l = tid; l < 32 * MDIM; l += THREADS)
            ((float*)(smem + PHIB(0)))[(l / MDIM) * 32 + (l % MDIM)] = phi[l];
    }
    __syncthreads();
    for (int kc = 0; kc < 32; kc++) {
        if (kc < 31) {
            int nb = (kc + 1) & 1, kb = (kc + 1) * 32;
            float* xs = (float*)(smem + XSB(nb));
            for (int r = 0; r < 2; r++) {
                int slot = r * THREADS + tid, tk = slot >> 3, kq = slot & 7;
                float4 v = *(const float4*)(x + (size_t)(tok0 + tk) * KDIM + kb + kq * 4);
                xs[(kq*4+0)*132 + tk] = v.x; xs[(kq*4+1)*132 + tk] = v.y;
                xs[(kq*4+2)*132 + tk] = v.z; xs[(kq*4+3)*132 + tk] = v.w;
            }
            float* ph = (float*)(smem + PHIB(nb));
            for (int l = tid; l < 32 * MDIM; l += THREADS)
                ph[(l / MDIM) * 32 + (l % MDIM)] = phi[kb * MDIM + l];
        }
        const float* xs = (const float*)(smem + XSB(kc & 1));
        const float* ph = (const float*)(smem + PHIB(kc & 1));
        #pragma unroll 8
        for (int k = 0; k < 32; k++) {
            float pm = ph[k * 32 + lane];
            u64 pm2 = pk2(pm, pm);
            ulonglong2 xa = *(const ulonglong2*)(&xs[k * 132 + t0]);
            ulonglong2 xb = *(const ulonglong2*)(&xs[k * 132 + t0 + 4]);
            acc2[0] = fma2(xa.x, pm2, acc2[0]);
            acc2[1] = fma2(xa.y, pm2, acc2[1]);
            acc2[2] = fma2(xb.x, pm2, acc2[2]);
            acc2[3] = fma2(xb.y, pm2, acc2[3]);
        }
        __syncthreads();
    }

    float l8[8];
    #pragma unroll
    for (int j = 0; j < 4; j++) upk2(acc2[j], l8[2*j], l8[2*j+1]);
    const float bm = (lane < MDIM) ? bvec[lane] : 0.0f;
    float yv[8];
    #pragma unroll
    for (int t = 0; t < 8; t++) {
        float s = (lane < MDIM) ? l8[t] * l8[t] : 0.0f;
        s += __shfl_xor_sync(~0u, s, 16); s += __shfl_xor_sync(~0u, s, 8);
        s += __shfl_xor_sync(~0u, s, 4);  s += __shfl_xor_sync(~0u, s, 2);
        s += __shfl_xor_sync(~0u, s, 1);
        yv[t] = l8[t] * rsqrtf(s * (1.0f / 24.0f) + RMS_EPS) + bm;
    }

    // ---------- Phase B: Sinkhorn ----------
    float P[4];
    #pragma unroll
    for (int tp = 0; tp < 4; tp++) {
        int src = 8 + (lane & 15);
        float ra = __shfl_sync(~0u, yv[2*tp], src);
        float rb = __shfl_sync(~0u, yv[2*tp+1], src);
        P[tp] = __expf(ares * ((lane < 16) ? ra : rb));
    }
    #pragma unroll
    for (int it = 0; it < TMAX_IT; it++) {
        #pragma unroll
        for (int tp = 0; tp < 4; tp++) {
            float s1 = P[tp] + __shfl_xor_sync(~0u, P[tp], 1);
            s1 += __shfl_xor_sync(~0u, s1, 2);
            P[tp] = __fdividef(P[tp], s1 + SINK_EPS);
        }
        #pragma unroll
        for (int tp = 0; tp < 4; tp++) {
            float s1 = P[tp] + __shfl_xor_sync(~0u, P[tp], 4);
            s1 += __shfl_xor_sync(~0u, s1, 8);
            P[tp] = __fdividef(P[tp], s1 + SINK_EPS);
        }
    }
    #pragma unroll
    for (int tp = 0; tp < 4; tp++) {
        int tl = t0 + 2*tp;
        if (lane < 16) s_cs[tl * 20 + lane] = P[tp];
        else           s_cs[(tl + 1) * 20 + (lane - 16)] = P[tp];
    }

    // ---------- Phase C: h_post + xin -> A tiles (bf16 hi/lo, row-major pad 264) ----------
    #pragma unroll
    for (int t = 0; t < 8; t++) {
        int tl = t0 + t, tok = tok0 + tl;
        float yp = __shfl_sync(~0u, yv[t], 4 + (lane & 3));
        if (lane < 4) s_cs[tl * 20 + 16 + lane] = POST_MULT * sigmoidf_fast(apost * yp);
        float hp0 = sigmoidf_fast(apre * __shfl_sync(~0u, yv[t], 0));
        float hp1 = sigmoidf_fast(apre * __shfl_sync(~0u, yv[t], 1));
        float hp2 = sigmoidf_fast(apre * __shfl_sync(~0u, yv[t], 2));
        float hp3 = sigmoidf_fast(apre * __shfl_sync(~0u, yv[t], 3));
        const float4* xt = (const float4*)(x + (size_t)tok * KDIM);
        float4 sA = make_float4(0,0,0,0), sB = make_float4(0,0,0,0);
        #pragma unroll
        for (int i = 0; i < HC; i++) {
            float hp = (i==0)?hp0:(i==1)?hp1:(i==2)?hp2:hp3;
            float4 a = xt[i * 64 + lane], b = xt[i * 64 + 32 + lane];
            sA.x = fmaf(hp,a.x,sA.x); sA.y = fmaf(hp,a.y,sA.y);
            sA.z = fmaf(hp,a.z,sA.z); sA.w = fmaf(hp,a.w,sA.w);
            sB.x = fmaf(hp,b.x,sB.x); sB.y = fmaf(hp,b.y,sB.y);
            sB.z = fmaf(hp,b.z,sB.z); sB.w = fmaf(hp,b.w,sB.w);
        }
        uint2 hA, lA, hB, lB;
        split4(sA, hA, lA); split4(sB, hB, lB);
        // cols 4*lane (bytes 8*lane) and 128+4*lane (bytes 256+8*lane)
        *(uint2*)(smem + OFF_AH + tl*A_STR + lane*8)       = hA;
        *(uint2*)(smem + OFF_AL + tl*A_STR + lane*8)       = lA;
        *(uint2*)(smem + OFF_AH + tl*A_STR + 256 + lane*8) = hB;
        *(uint2*)(smem + OFF_AL + tl*A_STR + 256 + lane*8) = lB;
    }
    __syncthreads();

    // ---------- Phase D: F = xin @ W^T via mma.sync bf16 (3-product split) ----------
    const int mt = wid & 7;        // m-tile (16 rows)
    const int nh = wid >> 3;       // n half: subtiles nh*16 .. nh*16+15
    float4 D[16];
    #pragma unroll
    for (int j = 0; j < 16; j++) D[j] = make_float4(0,0,0,0);

    const char* pah = smem + OFF_AH + (mt*16 + (lane>>2))*A_STR + (lane&3)*4;
    const char* pal = smem + OFF_AL + (mt*16 + (lane>>2))*A_STR + (lane&3)*4;

    for (int kc = 0; kc < 4; kc++) {
        // copy 64 KB packed W chunk into smem
        {
            const uint4* src = (const uint4*)(g_wpk + kc * 65536);
            uint4* dst = (uint4*)(smem + OFF_B);
            #pragma unroll
            for (int j = 0; j < 8; j++) dst[j * THREADS + tid] = src[j * THREADS + tid];
        }
        __syncthreads();
        #pragma unroll
        for (int ks = 0; ks < 4; ks++) {
            int gko = (kc * 4 + ks) * 32;   // byte offset of kstep in A row
            uint4 Ah, Al;
            Ah.x = *(const uint32_t*)(pah + gko);
            Ah.y = *(const uint32_t*)(pah + 8*A_STR + gko);
            Ah.z = *(const uint32_t*)(pah + gko + 16);
            Ah.w = *(const uint32_t*)(pah + 8*A_STR + gko + 16);
            Al.x = *(const uint32_t*)(pal + gko);
            Al.y = *(const uint32_t*)(pal + 8*A_STR + gko);
            Al.z = *(const uint32_t*)(pal + gko + 16);
            Al.w = *(const uint32_t*)(pal + 8*A_STR + gko + 16);
            const char* pb = smem + OFF_B + ((ks*32 + nh*16)*32 + lane)*8;
            #pragma unroll
            for (int j = 0; j < 16; j++) {
                uint2 bh = *(const uint2*)(pb + j*256);
                uint2 bl = *(const uint2*)(pb + 32768 + j*256);
                mma_bf16(D[j], Ah, bh);
                mma_bf16(D[j], Al, bh);
                mma_bf16(D[j], Ah, bl);
            }
        }
        __syncthreads();
    }

    // ---------- stage F into s_D fp32 [128][264] ----------
    float* sD = (float*)(smem + OFF_D);
    {
        int r0 = mt*16 + (lane>>2);
        int cb = nh*128 + (lane&3)*2;
        #pragma unroll
        for (int j = 0; j < 16; j++) {
            int col = cb + j*8;
            *(float2*)&sD[r0*D_STR + col]     = make_float2(D[j].x, D[j].y);
            *(float2*)&sD[(r0+8)*D_STR + col] = make_float2(D[j].z, D[j].w);
        }
    }
    __syncthreads();

    // ---------- epilogue: out = P@x + hpost * f ----------
    const int cx = lane;
    #pragma unroll
    for (int i = 0; i < 8; i++) {
        int tl = t0 + i, tok = tok0 + tl;
        const u64* xb = (const u64*)(x + (size_t)tok * KDIM);
        ulonglong2 xpA[HC], xpB[HC];
        #pragma unroll
        for (int ii = 0; ii < HC; ii++) {
            xpA[ii] = *(const ulonglong2*)(xb + ii * 128 + cx * 2);
            xpB[ii] = *(const ulonglong2*)(xb + ii * 128 + 64 + cx * 2);
        }
        float4 fA = *(const float4*)(sD + tl * D_STR + 4 * cx);
        float4 fB = *(const float4*)(sD + tl * D_STR + 128 + 4 * cx);
        u64* ob = (u64*)(out + (size_t)tok * KDIM);
        #pragma unroll
        for (int o = 0; o < HC; o++) {
            float hp = s_cs[tl * 20 + 16 + o];
            u64 hp2 = pk2(hp, hp);
            u64 r0 = fma2(hp2, pk2(fA.x, fA.y), 0ull);
            u64 r1 = fma2(hp2, pk2(fA.z, fA.w), 0ull);
            u64 r2 = fma2(hp2, pk2(fB.x, fB.y), 0ull);
            u64 r3 = fma2(hp2, pk2(fB.z, fB.w), 0ull);
            #pragma unroll
            for (int ii = 0; ii < HC; ii++) {
                float p = s_cs[tl * 20 + o * 4 + ii];
                u64 p2 = pk2(p, p);
                r0 = fma2(p2, xpA[ii].x, r0); r1 = fma2(p2, xpA[ii].y, r1);
                r2 = fma2(p2, xpB[ii].x, r2); r3 = fma2(p2, xpB[ii].y, r3);
            }
            *(ulonglong2*)(ob + o * 128 + cx * 2)      = make_ulonglong2(r0, r1);
            *(ulonglong2*)(ob + o * 128 + 64 + cx * 2) = make_ulonglong2(r2, r3);
        }
    }
}

// =====================================================================
extern "C" void kernel_launch(void* const* d_in, const int* in_sizes, int n_in,
                              void* d_out, int out_size)
{
    const float* x     = (const float*)d_in[0];
    const float* phi   = (const float*)d_in[1];
    const float* bvec  = (const float*)d_in[2];
    const float* apre  = (const float*)d_in[3];
    const float* apost = (const float*)d_in[4];
    const float* ares  = (const float*)d_in[5];
    const float* W     = (const float*)d_in[6];
    float* out = (float*)d_out;

    int tokens = in_sizes[0] / KDIM;

    static bool attr_set = false;
    if (!attr_set) {
        cudaFuncSetAttribute(mhc_mma, cudaFuncAttributeMaxDynamicSharedMemorySize, SMEM_TOTAL);
        attr_set = true;
    }
    w_pack<<<256, 256>>>(W);
    mhc_mma<<<tokens / TOK, THREADS, SMEM_TOTAL>>>(x, phi, bvec, apre, apost, ares, out);
}